// round 4
// baseline (speedup 1.0000x reference)
#include <cuda_runtime.h>
#include <math.h>

#define BATCH   8
#define CIN     1024
#define FEATC   1024
#define HH      18
#define WW      80
#define PP      (HH*WW)          // 1440
#define NTOT    (BATCH*PP)       // 11520
#define KDIM    (CIN*9)          // 9216
#define CLS3    96
#define REG3    416
#define CLS_TOTAL (BATCH*PP*CLS3)   // 1,105,920
#define REG_TOTAL (BATCH*PP*REG3)   // 4,792,320

// ---------------- scratch (device globals; no allocations) ----------------
__device__ float g_colbuf[(size_t)KDIM * NTOT];   // 424.7 MB, reused by every conv
__device__ float g_featT[(size_t)CIN * NTOT];     // features in [c][b*PP+p] layout
__device__ float g_h1[(size_t)FEATC * NTOT];
__device__ float g_h2[(size_t)FEATC * NTOT];
__device__ float g_r1[(size_t)FEATC * NTOT];
__device__ float g_r2[(size_t)FEATC * NTOT];
__device__ float g_offs[27 * NTOT];
__device__ float g_out3[(size_t)REG3 * NTOT];

__device__ __forceinline__ float* out_by_id(int id) {
    switch (id) {
        case 0: return g_h1;
        case 1: return g_h2;
        case 2: return g_r1;
        case 3: return g_r2;
        case 4: return g_offs;
        default: return g_out3;
    }
}
__device__ __forceinline__ const float* src_by_id(int id) {
    switch (id) {
        case 0: return g_featT;
        case 1: return g_h1;
        case 2: return g_h2;
        case 3: return g_r1;
        default: return g_r2;
    }
}

// ---------------- layout change: (B,C,H,W) -> [c][b*PP+p] ----------------
__global__ void transpose_feat(const float* __restrict__ src) {
    long long idx = (long long)blockIdx.x * blockDim.x + threadIdx.x;
    if (idx >= (long long)CIN * NTOT) return;
    int n = (int)(idx % NTOT);
    int c = (int)(idx / NTOT);
    int b = n / PP, p = n % PP;
    g_featT[idx] = src[((size_t)b * CIN + c) * PP + p];
}

// ---------------- im2col: src [1024][NTOT] -> colbuf[(c*9+tap)][NTOT] ----------------
__global__ void im2col_k(int src_id) {
    long long idx = (long long)blockIdx.x * blockDim.x + threadIdx.x;
    if (idx >= (long long)KDIM * NTOT) return;
    int n = (int)(idx % NTOT);
    long long r = idx / NTOT;
    int tap = (int)(r % 9);
    int c = (int)(r / 9);
    int b = n / PP, p = n % PP;
    int y = p / WW, x = p % WW;
    int yy = y + tap / 3 - 1;
    int xx = x + tap % 3 - 1;
    float v = 0.f;
    if (yy >= 0 && yy < HH && xx >= 0 && xx < WW)
        v = src_by_id(src_id)[(size_t)c * NTOT + b * PP + yy * WW + xx];
    g_colbuf[idx] = v;
}

// ---------------- deformable gather: featT + offsets -> colbuf ----------------
// block = (tap, y, b), threads (80 x-positions, 4 channel lanes)
__global__ void dcn_gather() {
    int tap = blockIdx.x;
    int y   = blockIdx.y;
    int b   = blockIdx.z;
    int x   = threadIdx.x;   // 0..79
    int cy  = threadIdx.y;   // 0..3
    int p = y * WW + x;
    int n = b * PP + p;

    float dy = g_offs[tap * NTOT + n];
    float dx = g_offs[(9 + tap) * NTOT + n];
    float m  = g_offs[(18 + tap) * NTOT + n];   // already sigmoided in GEMM epilogue

    float py = (float)y - 1.f + (float)(tap / 3) + dy;
    float px = (float)x - 1.f + (float)(tap % 3) + dx;
    float y0f = floorf(py), x0f = floorf(px);
    int y0 = (int)y0f, x0 = (int)x0f;
    float wy1 = py - y0f, wx1 = px - x0f;
    float wy0 = 1.f - wy1, wx0 = 1.f - wx1;

    bool vy0 = (y0 >= 0 && y0 < HH);
    bool vy1 = (y0 + 1 >= 0 && y0 + 1 < HH);
    bool vx0 = (x0 >= 0 && x0 < WW);
    bool vx1 = (x0 + 1 >= 0 && x0 + 1 < WW);
    int y0c = min(max(y0, 0), HH - 1);
    int y1c = min(max(y0 + 1, 0), HH - 1);
    int x0c = min(max(x0, 0), WW - 1);
    int x1c = min(max(x0 + 1, 0), WW - 1);

    float w00 = (vy0 && vx0) ? wy0 * wx0 * m : 0.f;
    float w01 = (vy0 && vx1) ? wy0 * wx1 * m : 0.f;
    float w10 = (vy1 && vx0) ? wy1 * wx0 * m : 0.f;
    float w11 = (vy1 && vx1) ? wy1 * wx1 * m : 0.f;
    int i00 = y0c * WW + x0c, i01 = y0c * WW + x1c;
    int i10 = y1c * WW + x0c, i11 = y1c * WW + x1c;

    for (int c = cy; c < CIN; c += 4) {
        const float* fp = g_featT + (size_t)c * NTOT + b * PP;
        float v = w00 * fp[i00] + w01 * fp[i01] + w10 * fp[i10] + w11 * fp[i11];
        g_colbuf[((size_t)c * 9 + tap) * NTOT + n] = v;
    }
}

// ---------------- SGEMM 128x128x8, 8x8 per thread, fused epilogue ----------------
// C[m][n] = act( sum_k A[m][k] * colbuf[k][n] + bias[m] ), optional BN
// MODE: 0 = bias only, 1 = bias+relu, 2 = bias->BN->relu, 3 = bias + sigmoid for m>=18
template <int MODE>
__global__ void __launch_bounds__(256, 2) gemm_epi(
    const float* __restrict__ A,
    const float* __restrict__ bias,
    const float* __restrict__ bng,
    const float* __restrict__ bnb,
    int M, int c_id)
{
    __shared__ float As[8][128];
    __shared__ float Bs[8][128];
    int t = threadIdx.x;
    int row0 = blockIdx.y * 128;
    int col0 = blockIdx.x * 128;

    int a_r = t >> 1;            // 0..127
    int a_c = (t & 1) * 4;       // 0 or 4
    int b_r = t >> 5;            // 0..7
    int b_c = (t & 31) * 4;      // 0..124

    bool a_ok = (row0 + a_r) < M;
    const float* Aptr = A + (size_t)(row0 + a_r) * KDIM + a_c;
    const float* Bptr = g_colbuf + (size_t)b_r * NTOT + col0 + b_c;

    float acc[8][8];
#pragma unroll
    for (int i = 0; i < 8; i++)
#pragma unroll
        for (int j = 0; j < 8; j++) acc[i][j] = 0.f;

    int tr = (t >> 4) * 8;
    int tc = (t & 15) * 8;

    for (int k0 = 0; k0 < KDIM; k0 += 8) {
        float4 av = a_ok ? *(const float4*)(Aptr + k0) : make_float4(0.f, 0.f, 0.f, 0.f);
        float4 bv = *(const float4*)(Bptr + (size_t)k0 * NTOT);
        As[a_c + 0][a_r] = av.x;
        As[a_c + 1][a_r] = av.y;
        As[a_c + 2][a_r] = av.z;
        As[a_c + 3][a_r] = av.w;
        *(float4*)&Bs[b_r][b_c] = bv;
        __syncthreads();
#pragma unroll
        for (int kk = 0; kk < 8; kk++) {
            float ar[8], br[8];
#pragma unroll
            for (int i = 0; i < 8; i++) ar[i] = As[kk][tr + i];
#pragma unroll
            for (int j = 0; j < 8; j++) br[j] = Bs[kk][tc + j];
#pragma unroll
            for (int i = 0; i < 8; i++)
#pragma unroll
                for (int j = 0; j < 8; j++) acc[i][j] = fmaf(ar[i], br[j], acc[i][j]);
        }
        __syncthreads();
    }

    float* C = out_by_id(c_id);
#pragma unroll
    for (int i = 0; i < 8; i++) {
        int m = row0 + tr + i;
        if (m >= M) continue;
        float bi = bias[m];
        float s = 1.f, sh = 0.f;
        if (MODE == 2) { s = bng[m] * rsqrtf(1.f + 1e-5f); sh = bnb[m]; }
#pragma unroll
        for (int j = 0; j < 8; j++) {
            float v = acc[i][j] + bi;
            if (MODE == 2) v = v * s + sh;
            if (MODE == 1 || MODE == 2) v = fmaxf(v, 0.f);
            if (MODE == 3 && m >= 18) v = 1.f / (1.f + expf(-v));
            C[(size_t)m * NTOT + col0 + tc + j] = v;
        }
    }
}

// ---------------- anchor_flatten writers ----------------
__global__ void write_cls(float* __restrict__ dout) {
    int idx = blockIdx.x * blockDim.x + threadIdx.x;
    if (idx >= CLS_TOTAL) return;
    int j = idx % 3;
    int r = idx / 3;
    int a = r % 32; r /= 32;
    int p = r % PP;
    int b = r / PP;
    int c = a * 3 + j;
    dout[idx] = g_out3[(size_t)c * NTOT + b * PP + p];
}

__global__ void write_reg(float* __restrict__ dout) {
    int idx = blockIdx.x * blockDim.x + threadIdx.x;
    if (idx >= REG_TOTAL) return;
    int j = idx % 13;
    int r = idx / 13;
    int a = r % 32; r /= 32;
    int p = r % PP;
    int b = r / PP;
    int c = a * 13 + j;
    dout[idx] = g_out3[(size_t)c * NTOT + b * PP + p];
}

// ---------------- launch ----------------
extern "C" void kernel_launch(void* const* d_in, const int* in_sizes, int n_in,
                              void* d_out, int out_size) {
    const float* features = (const float*)d_in[0];
    const float* cls_w1 = (const float*)d_in[1];
    const float* cls_b1 = (const float*)d_in[2];
    const float* cls_w2 = (const float*)d_in[3];
    const float* cls_b2 = (const float*)d_in[4];
    const float* cls_w3 = (const float*)d_in[5];
    const float* cls_b3 = (const float*)d_in[6];
    const float* off_w  = (const float*)d_in[7];
    const float* off_b  = (const float*)d_in[8];
    const float* dcn_w  = (const float*)d_in[9];
    const float* dcn_b  = (const float*)d_in[10];
    const float* bn1_g  = (const float*)d_in[11];
    const float* bn1_b  = (const float*)d_in[12];
    const float* reg_w2 = (const float*)d_in[13];
    const float* reg_b2 = (const float*)d_in[14];
    const float* bn2_g  = (const float*)d_in[15];
    const float* bn2_b  = (const float*)d_in[16];
    const float* reg_w3 = (const float*)d_in[17];
    const float* reg_b3 = (const float*)d_in[18];
    float* out = (float*)d_out;

    const int ntiles = NTOT / 128;      // 90
    dim3 g8(ntiles, 8), g1(ntiles, 1), g4(ntiles, 4);
    long long col_elems = (long long)KDIM * NTOT;
    int col_blocks = (int)((col_elems + 255) / 256);

    // features -> channel-major
    transpose_feat<<<(CIN * NTOT + 255) / 256, 256>>>(features);

    // shared im2col of features (serves offset conv + cls1)
    im2col_k<<<col_blocks, 256>>>(0);
    gemm_epi<3><<<g1, 256>>>(off_w, off_b, nullptr, nullptr, 27, 4);     // -> g_offs
    gemm_epi<1><<<g8, 256>>>(cls_w1, cls_b1, nullptr, nullptr, 1024, 0); // -> g_h1

    // deformable gather overwrites colbuf, then dcn GEMM (+bias, BN1, relu)
    dcn_gather<<<dim3(9, HH, BATCH), dim3(80, 4)>>>();
    gemm_epi<2><<<g8, 256>>>(dcn_w, dcn_b, bn1_g, bn1_b, 1024, 2);       // -> g_r1

    // cls branch tail
    im2col_k<<<col_blocks, 256>>>(1);                                    // from h1
    gemm_epi<1><<<g8, 256>>>(cls_w2, cls_b2, nullptr, nullptr, 1024, 1); // -> g_h2
    im2col_k<<<col_blocks, 256>>>(2);                                    // from h2
    gemm_epi<0><<<g1, 256>>>(cls_w3, cls_b3, nullptr, nullptr, CLS3, 5); // -> g_out3
    write_cls<<<(CLS_TOTAL + 255) / 256, 256>>>(out);

    // reg branch tail
    im2col_k<<<col_blocks, 256>>>(3);                                    // from r1
    gemm_epi<2><<<g8, 256>>>(reg_w2, reg_b2, bn2_g, bn2_b, 1024, 3);     // -> g_r2
    im2col_k<<<col_blocks, 256>>>(4);                                    // from r2
    gemm_epi<0><<<g4, 256>>>(reg_w3, reg_b3, nullptr, nullptr, REG3, 5); // -> g_out3
    write_reg<<<(REG_TOTAL + 255) / 256, 256>>>(out + CLS_TOTAL);
}

// round 5
// speedup vs baseline: 1.0020x; 1.0020x over previous
#include <cuda_runtime.h>
#include <math.h>

#define BATCH   8
#define CIN     1024
#define FEATC   1024
#define HH      18
#define WW      80
#define PP      (HH*WW)          // 1440
#define NTOT    (BATCH*PP)       // 11520
#define KDIM    (CIN*9)          // 9216
#define CLS3    96
#define REG3    416
#define CLS_TOTAL (BATCH*PP*CLS3)   // 1,105,920
#define REG_TOTAL (BATCH*PP*REG3)   // 4,792,320

// ---------------- scratch (device globals; no allocations) ----------------
__device__ float g_colbuf[(size_t)KDIM * NTOT];   // 424.7 MB, reused by every conv
__device__ float g_featT[(size_t)CIN * NTOT];     // features in [c][b*PP+p] layout
__device__ float g_h1[(size_t)FEATC * NTOT];
__device__ float g_h2[(size_t)FEATC * NTOT];
__device__ float g_r1[(size_t)FEATC * NTOT];
__device__ float g_r2[(size_t)FEATC * NTOT];
__device__ float g_offs[27 * NTOT];
__device__ float g_out3[(size_t)REG3 * NTOT];

__device__ __forceinline__ float* out_by_id(int id) {
    switch (id) {
        case 0: return g_h1;
        case 1: return g_h2;
        case 2: return g_r1;
        case 3: return g_r2;
        case 4: return g_offs;
        default: return g_out3;
    }
}
__device__ __forceinline__ const float* src_by_id(int id) {
    switch (id) {
        case 0: return g_featT;
        case 1: return g_h1;
        case 2: return g_h2;
        case 3: return g_r1;
        default: return g_r2;
    }
}

// ---------------- layout change: (B,C,H,W) -> [c][b*PP+p] ----------------
__global__ void transpose_feat(const float* __restrict__ src) {
    long long idx = (long long)blockIdx.x * blockDim.x + threadIdx.x;
    if (idx >= (long long)CIN * NTOT) return;
    int n = (int)(idx % NTOT);
    int c = (int)(idx / NTOT);
    int b = n / PP, p = n % PP;
    g_featT[idx] = src[((size_t)b * CIN + c) * PP + p];
}

// ---------------- im2col: src [1024][NTOT] -> colbuf[(c*9+tap)][NTOT] ----------------
__global__ void im2col_k(int src_id) {
    long long idx = (long long)blockIdx.x * blockDim.x + threadIdx.x;
    if (idx >= (long long)KDIM * NTOT) return;
    int n = (int)(idx % NTOT);
    long long r = idx / NTOT;
    int tap = (int)(r % 9);
    int c = (int)(r / 9);
    int b = n / PP, p = n % PP;
    int y = p / WW, x = p % WW;
    int yy = y + tap / 3 - 1;
    int xx = x + tap % 3 - 1;
    float v = 0.f;
    if (yy >= 0 && yy < HH && xx >= 0 && xx < WW)
        v = src_by_id(src_id)[(size_t)c * NTOT + b * PP + yy * WW + xx];
    g_colbuf[idx] = v;
}

// ---------------- deformable gather: featT + offsets -> colbuf ----------------
// block = (tap, y, b), threads (80 x-positions, 4 channel lanes)
__global__ void dcn_gather() {
    int tap = blockIdx.x;
    int y   = blockIdx.y;
    int b   = blockIdx.z;
    int x   = threadIdx.x;   // 0..79
    int cy  = threadIdx.y;   // 0..3
    int p = y * WW + x;
    int n = b * PP + p;

    float dy = g_offs[tap * NTOT + n];
    float dx = g_offs[(9 + tap) * NTOT + n];
    float m  = g_offs[(18 + tap) * NTOT + n];   // already sigmoided in GEMM epilogue

    float py = (float)y - 1.f + (float)(tap / 3) + dy;
    float px = (float)x - 1.f + (float)(tap % 3) + dx;
    float y0f = floorf(py), x0f = floorf(px);
    int y0 = (int)y0f, x0 = (int)x0f;
    float wy1 = py - y0f, wx1 = px - x0f;
    float wy0 = 1.f - wy1, wx0 = 1.f - wx1;

    bool vy0 = (y0 >= 0 && y0 < HH);
    bool vy1 = (y0 + 1 >= 0 && y0 + 1 < HH);
    bool vx0 = (x0 >= 0 && x0 < WW);
    bool vx1 = (x0 + 1 >= 0 && x0 + 1 < WW);
    int y0c = min(max(y0, 0), HH - 1);
    int y1c = min(max(y0 + 1, 0), HH - 1);
    int x0c = min(max(x0, 0), WW - 1);
    int x1c = min(max(x0 + 1, 0), WW - 1);

    float w00 = (vy0 && vx0) ? wy0 * wx0 * m : 0.f;
    float w01 = (vy0 && vx1) ? wy0 * wx1 * m : 0.f;
    float w10 = (vy1 && vx0) ? wy1 * wx0 * m : 0.f;
    float w11 = (vy1 && vx1) ? wy1 * wx1 * m : 0.f;
    int i00 = y0c * WW + x0c, i01 = y0c * WW + x1c;
    int i10 = y1c * WW + x0c, i11 = y1c * WW + x1c;

    for (int c = cy; c < CIN; c += 4) {
        const float* fp = g_featT + (size_t)c * NTOT + b * PP;
        float v = w00 * fp[i00] + w01 * fp[i01] + w10 * fp[i10] + w11 * fp[i11];
        g_colbuf[((size_t)c * 9 + tap) * NTOT + n] = v;
    }
}

// ---------------- SGEMM 128x128x8, 8x8 per thread, fused epilogue ----------------
// C[m][n] = act( sum_k A[m][k] * colbuf[k][n] + bias[m] ), optional BN
// MODE: 0 = bias only, 1 = bias+relu, 2 = bias->BN->relu, 3 = bias + sigmoid for m>=18
template <int MODE>
__global__ void __launch_bounds__(256, 2) gemm_epi(
    const float* __restrict__ A,
    const float* __restrict__ bias,
    const float* __restrict__ bng,
    const float* __restrict__ bnb,
    int M, int c_id)
{
    __shared__ float As[8][128];
    __shared__ float Bs[8][128];
    int t = threadIdx.x;
    int row0 = blockIdx.y * 128;
    int col0 = blockIdx.x * 128;

    int a_r = t >> 1;            // 0..127
    int a_c = (t & 1) * 4;       // 0 or 4
    int b_r = t >> 5;            // 0..7
    int b_c = (t & 31) * 4;      // 0..124

    bool a_ok = (row0 + a_r) < M;
    const float* Aptr = A + (size_t)(row0 + a_r) * KDIM + a_c;
    const float* Bptr = g_colbuf + (size_t)b_r * NTOT + col0 + b_c;

    float acc[8][8];
#pragma unroll
    for (int i = 0; i < 8; i++)
#pragma unroll
        for (int j = 0; j < 8; j++) acc[i][j] = 0.f;

    int tr = (t >> 4) * 8;
    int tc = (t & 15) * 8;

    for (int k0 = 0; k0 < KDIM; k0 += 8) {
        float4 av = a_ok ? *(const float4*)(Aptr + k0) : make_float4(0.f, 0.f, 0.f, 0.f);
        float4 bv = *(const float4*)(Bptr + (size_t)k0 * NTOT);
        As[a_c + 0][a_r] = av.x;
        As[a_c + 1][a_r] = av.y;
        As[a_c + 2][a_r] = av.z;
        As[a_c + 3][a_r] = av.w;
        *(float4*)&Bs[b_r][b_c] = bv;
        __syncthreads();
#pragma unroll
        for (int kk = 0; kk < 8; kk++) {
            float ar[8], br[8];
#pragma unroll
            for (int i = 0; i < 8; i++) ar[i] = As[kk][tr + i];
#pragma unroll
            for (int j = 0; j < 8; j++) br[j] = Bs[kk][tc + j];
#pragma unroll
            for (int i = 0; i < 8; i++)
#pragma unroll
                for (int j = 0; j < 8; j++) acc[i][j] = fmaf(ar[i], br[j], acc[i][j]);
        }
        __syncthreads();
    }

    float* C = out_by_id(c_id);
#pragma unroll
    for (int i = 0; i < 8; i++) {
        int m = row0 + tr + i;
        if (m >= M) continue;
        float bi = bias[m];
        float s = 1.f, sh = 0.f;
        if (MODE == 2) { s = bng[m] * rsqrtf(1.f + 1e-5f); sh = bnb[m]; }
#pragma unroll
        for (int j = 0; j < 8; j++) {
            float v = acc[i][j] + bi;
            if (MODE == 2) v = v * s + sh;
            if (MODE == 1 || MODE == 2) v = fmaxf(v, 0.f);
            if (MODE == 3 && m >= 18) v = 1.f / (1.f + expf(-v));
            C[(size_t)m * NTOT + col0 + tc + j] = v;
        }
    }
}

// ---------------- anchor_flatten writers ----------------
__global__ void write_cls(float* __restrict__ dout) {
    int idx = blockIdx.x * blockDim.x + threadIdx.x;
    if (idx >= CLS_TOTAL) return;
    int j = idx % 3;
    int r = idx / 3;
    int a = r % 32; r /= 32;
    int p = r % PP;
    int b = r / PP;
    int c = a * 3 + j;
    dout[idx] = g_out3[(size_t)c * NTOT + b * PP + p];
}

__global__ void write_reg(float* __restrict__ dout) {
    int idx = blockIdx.x * blockDim.x + threadIdx.x;
    if (idx >= REG_TOTAL) return;
    int j = idx % 13;
    int r = idx / 13;
    int a = r % 32; r /= 32;
    int p = r % PP;
    int b = r / PP;
    int c = a * 13 + j;
    dout[idx] = g_out3[(size_t)c * NTOT + b * PP + p];
}

// ---------------- launch ----------------
extern "C" void kernel_launch(void* const* d_in, const int* in_sizes, int n_in,
                              void* d_out, int out_size) {
    const float* features = (const float*)d_in[0];
    const float* cls_w1 = (const float*)d_in[1];
    const float* cls_b1 = (const float*)d_in[2];
    const float* cls_w2 = (const float*)d_in[3];
    const float* cls_b2 = (const float*)d_in[4];
    const float* cls_w3 = (const float*)d_in[5];
    const float* cls_b3 = (const float*)d_in[6];
    const float* off_w  = (const float*)d_in[7];
    const float* off_b  = (const float*)d_in[8];
    const float* dcn_w  = (const float*)d_in[9];
    const float* dcn_b  = (const float*)d_in[10];
    const float* bn1_g  = (const float*)d_in[11];
    const float* bn1_b  = (const float*)d_in[12];
    const float* reg_w2 = (const float*)d_in[13];
    const float* reg_b2 = (const float*)d_in[14];
    const float* bn2_g  = (const float*)d_in[15];
    const float* bn2_b  = (const float*)d_in[16];
    const float* reg_w3 = (const float*)d_in[17];
    const float* reg_b3 = (const float*)d_in[18];
    float* out = (float*)d_out;

    const int ntiles = NTOT / 128;      // 90
    dim3 g8(ntiles, 8), g1(ntiles, 1), g4(ntiles, 4);
    long long col_elems = (long long)KDIM * NTOT;
    int col_blocks = (int)((col_elems + 255) / 256);

    // features -> channel-major
    transpose_feat<<<(CIN * NTOT + 255) / 256, 256>>>(features);

    // shared im2col of features (serves offset conv + cls1)
    im2col_k<<<col_blocks, 256>>>(0);
    gemm_epi<3><<<g1, 256>>>(off_w, off_b, nullptr, nullptr, 27, 4);     // -> g_offs
    gemm_epi<1><<<g8, 256>>>(cls_w1, cls_b1, nullptr, nullptr, 1024, 0); // -> g_h1

    // deformable gather overwrites colbuf, then dcn GEMM (+bias, BN1, relu)
    dcn_gather<<<dim3(9, HH, BATCH), dim3(80, 4)>>>();
    gemm_epi<2><<<g8, 256>>>(dcn_w, dcn_b, bn1_g, bn1_b, 1024, 2);       // -> g_r1

    // cls branch tail
    im2col_k<<<col_blocks, 256>>>(1);                                    // from h1
    gemm_epi<1><<<g8, 256>>>(cls_w2, cls_b2, nullptr, nullptr, 1024, 1); // -> g_h2
    im2col_k<<<col_blocks, 256>>>(2);                                    // from h2
    gemm_epi<0><<<g1, 256>>>(cls_w3, cls_b3, nullptr, nullptr, CLS3, 5); // -> g_out3
    write_cls<<<(CLS_TOTAL + 255) / 256, 256>>>(out);

    // reg branch tail
    im2col_k<<<col_blocks, 256>>>(3);                                    // from r1
    gemm_epi<2><<<g8, 256>>>(reg_w2, reg_b2, bn2_g, bn2_b, 1024, 3);     // -> g_r2
    im2col_k<<<col_blocks, 256>>>(4);                                    // from r2
    gemm_epi<0><<<g4, 256>>>(reg_w3, reg_b3, nullptr, nullptr, REG3, 5); // -> g_out3
    write_reg<<<(REG_TOTAL + 255) / 256, 256>>>(out + CLS_TOTAL);
}

// round 6
// speedup vs baseline: 1.0039x; 1.0018x over previous
#include <cuda_runtime.h>
#include <math.h>

#define BATCH   8
#define CIN     1024
#define FEATC   1024
#define HH      18
#define WW      80
#define PP      (HH*WW)          // 1440
#define NTOT    (BATCH*PP)       // 11520
#define KDIM    (CIN*9)          // 9216
#define CLS3    96
#define REG3    416
#define CLS_TOTAL (BATCH*PP*CLS3)   // 1,105,920
#define REG_TOTAL (BATCH*PP*REG3)   // 4,792,320

// ---------------- scratch (device globals; no allocations) ----------------
__device__ float g_colbuf[(size_t)KDIM * NTOT];   // 424.7 MB, reused by every conv
__device__ float g_featT[(size_t)CIN * NTOT];     // features in [c][b*PP+p] layout
__device__ float g_h1[(size_t)FEATC * NTOT];
__device__ float g_h2[(size_t)FEATC * NTOT];
__device__ float g_r1[(size_t)FEATC * NTOT];
__device__ float g_r2[(size_t)FEATC * NTOT];
__device__ float g_offs[27 * NTOT];
__device__ float g_out3[(size_t)REG3 * NTOT];

__device__ __forceinline__ float* out_by_id(int id) {
    switch (id) {
        case 0: return g_h1;
        case 1: return g_h2;
        case 2: return g_r1;
        case 3: return g_r2;
        case 4: return g_offs;
        default: return g_out3;
    }
}
__device__ __forceinline__ const float* src_by_id(int id) {
    switch (id) {
        case 0: return g_featT;
        case 1: return g_h1;
        case 2: return g_h2;
        case 3: return g_r1;
        default: return g_r2;
    }
}

// ---------------- layout change: (B,C,H,W) -> [c][b*PP+p] ----------------
__global__ void transpose_feat(const float* __restrict__ src) {
    long long idx = (long long)blockIdx.x * blockDim.x + threadIdx.x;
    if (idx >= (long long)CIN * NTOT) return;
    int n = (int)(idx % NTOT);
    int c = (int)(idx / NTOT);
    int b = n / PP, p = n % PP;
    g_featT[idx] = src[((size_t)b * CIN + c) * PP + p];
}

// ---------------- im2col: src [1024][NTOT] -> colbuf[(c*9+tap)][NTOT] ----------------
__global__ void im2col_k(int src_id) {
    long long idx = (long long)blockIdx.x * blockDim.x + threadIdx.x;
    if (idx >= (long long)KDIM * NTOT) return;
    int n = (int)(idx % NTOT);
    long long r = idx / NTOT;
    int tap = (int)(r % 9);
    int c = (int)(r / 9);
    int b = n / PP, p = n % PP;
    int y = p / WW, x = p % WW;
    int yy = y + tap / 3 - 1;
    int xx = x + tap % 3 - 1;
    float v = 0.f;
    if (yy >= 0 && yy < HH && xx >= 0 && xx < WW)
        v = src_by_id(src_id)[(size_t)c * NTOT + b * PP + yy * WW + xx];
    g_colbuf[idx] = v;
}

// ---------------- deformable gather: featT + offsets -> colbuf ----------------
// block = (tap, y, b), threads (80 x-positions, 4 channel lanes)
__global__ void dcn_gather() {
    int tap = blockIdx.x;
    int y   = blockIdx.y;
    int b   = blockIdx.z;
    int x   = threadIdx.x;   // 0..79
    int cy  = threadIdx.y;   // 0..3
    int p = y * WW + x;
    int n = b * PP + p;

    float dy = g_offs[tap * NTOT + n];
    float dx = g_offs[(9 + tap) * NTOT + n];
    float m  = g_offs[(18 + tap) * NTOT + n];   // already sigmoided in GEMM epilogue

    float py = (float)y - 1.f + (float)(tap / 3) + dy;
    float px = (float)x - 1.f + (float)(tap % 3) + dx;
    float y0f = floorf(py), x0f = floorf(px);
    int y0 = (int)y0f, x0 = (int)x0f;
    float wy1 = py - y0f, wx1 = px - x0f;
    float wy0 = 1.f - wy1, wx0 = 1.f - wx1;

    bool vy0 = (y0 >= 0 && y0 < HH);
    bool vy1 = (y0 + 1 >= 0 && y0 + 1 < HH);
    bool vx0 = (x0 >= 0 && x0 < WW);
    bool vx1 = (x0 + 1 >= 0 && x0 + 1 < WW);
    int y0c = min(max(y0, 0), HH - 1);
    int y1c = min(max(y0 + 1, 0), HH - 1);
    int x0c = min(max(x0, 0), WW - 1);
    int x1c = min(max(x0 + 1, 0), WW - 1);

    float w00 = (vy0 && vx0) ? wy0 * wx0 * m : 0.f;
    float w01 = (vy0 && vx1) ? wy0 * wx1 * m : 0.f;
    float w10 = (vy1 && vx0) ? wy1 * wx0 * m : 0.f;
    float w11 = (vy1 && vx1) ? wy1 * wx1 * m : 0.f;
    int i00 = y0c * WW + x0c, i01 = y0c * WW + x1c;
    int i10 = y1c * WW + x0c, i11 = y1c * WW + x1c;

    for (int c = cy; c < CIN; c += 4) {
        const float* fp = g_featT + (size_t)c * NTOT + b * PP;
        float v = w00 * fp[i00] + w01 * fp[i01] + w10 * fp[i10] + w11 * fp[i11];
        g_colbuf[((size_t)c * 9 + tap) * NTOT + n] = v;
    }
}

// ---------------- SGEMM 128x128x8, 8x8 per thread, fused epilogue ----------------
// C[m][n] = act( sum_k A[m][k] * colbuf[k][n] + bias[m] ), optional BN
// MODE: 0 = bias only, 1 = bias+relu, 2 = bias->BN->relu, 3 = bias + sigmoid for m>=18
template <int MODE>
__global__ void __launch_bounds__(256, 2) gemm_epi(
    const float* __restrict__ A,
    const float* __restrict__ bias,
    const float* __restrict__ bng,
    const float* __restrict__ bnb,
    int M, int c_id)
{
    __shared__ float As[8][128];
    __shared__ float Bs[8][128];
    int t = threadIdx.x;
    int row0 = blockIdx.y * 128;
    int col0 = blockIdx.x * 128;

    int a_r = t >> 1;            // 0..127
    int a_c = (t & 1) * 4;       // 0 or 4
    int b_r = t >> 5;            // 0..7
    int b_c = (t & 31) * 4;      // 0..124

    bool a_ok = (row0 + a_r) < M;
    const float* Aptr = A + (size_t)(row0 + a_r) * KDIM + a_c;
    const float* Bptr = g_colbuf + (size_t)b_r * NTOT + col0 + b_c;

    float acc[8][8];
#pragma unroll
    for (int i = 0; i < 8; i++)
#pragma unroll
        for (int j = 0; j < 8; j++) acc[i][j] = 0.f;

    int tr = (t >> 4) * 8;
    int tc = (t & 15) * 8;

    for (int k0 = 0; k0 < KDIM; k0 += 8) {
        float4 av = a_ok ? *(const float4*)(Aptr + k0) : make_float4(0.f, 0.f, 0.f, 0.f);
        float4 bv = *(const float4*)(Bptr + (size_t)k0 * NTOT);
        As[a_c + 0][a_r] = av.x;
        As[a_c + 1][a_r] = av.y;
        As[a_c + 2][a_r] = av.z;
        As[a_c + 3][a_r] = av.w;
        *(float4*)&Bs[b_r][b_c] = bv;
        __syncthreads();
#pragma unroll
        for (int kk = 0; kk < 8; kk++) {
            float ar[8], br[8];
#pragma unroll
            for (int i = 0; i < 8; i++) ar[i] = As[kk][tr + i];
#pragma unroll
            for (int j = 0; j < 8; j++) br[j] = Bs[kk][tc + j];
#pragma unroll
            for (int i = 0; i < 8; i++)
#pragma unroll
                for (int j = 0; j < 8; j++) acc[i][j] = fmaf(ar[i], br[j], acc[i][j]);
        }
        __syncthreads();
    }

    float* C = out_by_id(c_id);
#pragma unroll
    for (int i = 0; i < 8; i++) {
        int m = row0 + tr + i;
        if (m >= M) continue;
        float bi = bias[m];
        float s = 1.f, sh = 0.f;
        if (MODE == 2) { s = bng[m] * rsqrtf(1.f + 1e-5f); sh = bnb[m]; }
#pragma unroll
        for (int j = 0; j < 8; j++) {
            float v = acc[i][j] + bi;
            if (MODE == 2) v = v * s + sh;
            if (MODE == 1 || MODE == 2) v = fmaxf(v, 0.f);
            if (MODE == 3 && m >= 18) v = 1.f / (1.f + expf(-v));
            C[(size_t)m * NTOT + col0 + tc + j] = v;
        }
    }
}

// ---------------- anchor_flatten writers ----------------
__global__ void write_cls(float* __restrict__ dout) {
    int idx = blockIdx.x * blockDim.x + threadIdx.x;
    if (idx >= CLS_TOTAL) return;
    int j = idx % 3;
    int r = idx / 3;
    int a = r % 32; r /= 32;
    int p = r % PP;
    int b = r / PP;
    int c = a * 3 + j;
    dout[idx] = g_out3[(size_t)c * NTOT + b * PP + p];
}

__global__ void write_reg(float* __restrict__ dout) {
    int idx = blockIdx.x * blockDim.x + threadIdx.x;
    if (idx >= REG_TOTAL) return;
    int j = idx % 13;
    int r = idx / 13;
    int a = r % 32; r /= 32;
    int p = r % PP;
    int b = r / PP;
    int c = a * 13 + j;
    dout[idx] = g_out3[(size_t)c * NTOT + b * PP + p];
}

// ---------------- launch ----------------
extern "C" void kernel_launch(void* const* d_in, const int* in_sizes, int n_in,
                              void* d_out, int out_size) {
    const float* features = (const float*)d_in[0];
    const float* cls_w1 = (const float*)d_in[1];
    const float* cls_b1 = (const float*)d_in[2];
    const float* cls_w2 = (const float*)d_in[3];
    const float* cls_b2 = (const float*)d_in[4];
    const float* cls_w3 = (const float*)d_in[5];
    const float* cls_b3 = (const float*)d_in[6];
    const float* off_w  = (const float*)d_in[7];
    const float* off_b  = (const float*)d_in[8];
    const float* dcn_w  = (const float*)d_in[9];
    const float* dcn_b  = (const float*)d_in[10];
    const float* bn1_g  = (const float*)d_in[11];
    const float* bn1_b  = (const float*)d_in[12];
    const float* reg_w2 = (const float*)d_in[13];
    const float* reg_b2 = (const float*)d_in[14];
    const float* bn2_g  = (const float*)d_in[15];
    const float* bn2_b  = (const float*)d_in[16];
    const float* reg_w3 = (const float*)d_in[17];
    const float* reg_b3 = (const float*)d_in[18];
    float* out = (float*)d_out;

    const int ntiles = NTOT / 128;      // 90
    dim3 g8(ntiles, 8), g1(ntiles, 1), g4(ntiles, 4);
    long long col_elems = (long long)KDIM * NTOT;
    int col_blocks = (int)((col_elems + 255) / 256);

    // features -> channel-major
    transpose_feat<<<(CIN * NTOT + 255) / 256, 256>>>(features);

    // shared im2col of features (serves offset conv + cls1)
    im2col_k<<<col_blocks, 256>>>(0);
    gemm_epi<3><<<g1, 256>>>(off_w, off_b, nullptr, nullptr, 27, 4);     // -> g_offs
    gemm_epi<1><<<g8, 256>>>(cls_w1, cls_b1, nullptr, nullptr, 1024, 0); // -> g_h1

    // deformable gather overwrites colbuf, then dcn GEMM (+bias, BN1, relu)
    dcn_gather<<<dim3(9, HH, BATCH), dim3(80, 4)>>>();
    gemm_epi<2><<<g8, 256>>>(dcn_w, dcn_b, bn1_g, bn1_b, 1024, 2);       // -> g_r1

    // cls branch tail
    im2col_k<<<col_blocks, 256>>>(1);                                    // from h1
    gemm_epi<1><<<g8, 256>>>(cls_w2, cls_b2, nullptr, nullptr, 1024, 1); // -> g_h2
    im2col_k<<<col_blocks, 256>>>(2);                                    // from h2
    gemm_epi<0><<<g1, 256>>>(cls_w3, cls_b3, nullptr, nullptr, CLS3, 5); // -> g_out3
    write_cls<<<(CLS_TOTAL + 255) / 256, 256>>>(out);

    // reg branch tail
    im2col_k<<<col_blocks, 256>>>(3);                                    // from r1
    gemm_epi<2><<<g8, 256>>>(reg_w2, reg_b2, bn2_g, bn2_b, 1024, 3);     // -> g_r2
    im2col_k<<<col_blocks, 256>>>(4);                                    // from r2
    gemm_epi<0><<<g4, 256>>>(reg_w3, reg_b3, nullptr, nullptr, REG3, 5); // -> g_out3
    write_reg<<<(REG_TOTAL + 255) / 256, 256>>>(out + CLS_TOTAL);
}